// round 6
// baseline (speedup 1.0000x reference)
#include <cuda_runtime.h>
#include <cuda_bf16.h>
#include <cstdint>

// ===========================================================================
// HierarchicalDownTopFusion — mma.sync bf16 3-term split, cp.async pipelined,
// ILP-reordered MMA issue (same-acc reuse distance 8).
//   medium_pooled = mean_m(medium) + (0.25*sum_m GELU(LN(pool_m@W1+b1))) @ W2 + b2
//   out           = global + MLP2(medium_pooled)
// ===========================================================================

#define BN 65536
#define DD 768
#define HH 256
#define NT 256
#define LN_EPS 1e-5f
#define SWZ(o) ((o) ^ (((o) >> 3) & 0x70))

// ---- K1 SMEM layout (bytes) ----
#define K1_A(b)   ((b) * 32768)             // AHI +0 (16K), ALO +16384
#define K1_B(b)   (65536 + (b) * 65536)     // BHI +0 (32K), BLO +32768
#define K1_GS     196608                    // f32 [32][256] = 32K
#define K1_RED    229376                    // RS[256]+RQ[256] = 2K
#define K1_SMEM   231424

// ---- K2 SMEM layout ----
#define K2_A(b)   ((b) * 16384)             // AHI +0 (8K), ALO +8192
#define K2_B(b)   (32768 + (b) * 65536)     // BHI +0 (32K), BLO +32768
#define K2_GSH    163840                    // 4 chunks x [64][128B] = 32K
#define K2_GSL    196608                    // 32K
#define K2_RED    229376                    // 2K
#define K2_SMEM   231424

// ---------------- device globals (allocation-guard safe) ----------------
__device__ __align__(16) __nv_bfloat16 g_mp_hi[(size_t)BN * DD];
__device__ __align__(16) __nv_bfloat16 g_mp_lo[(size_t)BN * DD];
__device__ __align__(16) __nv_bfloat16 g_w1t_hi[2][HH * DD];
__device__ __align__(16) __nv_bfloat16 g_w1t_lo[2][HH * DD];
__device__ __align__(16) __nv_bfloat16 g_w2t_hi[2][DD * HH];
__device__ __align__(16) __nv_bfloat16 g_w2t_lo[2][DD * HH];

// ---------------- low-level helpers ----------------
__device__ __forceinline__ uint32_t smem_u32(const void* p) {
    uint32_t a;
    asm("{ .reg .u64 t; cvta.to.shared.u64 t, %1; cvt.u32.u64 %0, t; }"
        : "=r"(a) : "l"(p));
    return a;
}
#define CP_ASYNC16(dst, src) \
    asm volatile("cp.async.cg.shared.global [%0], [%1], 16;" \
                 :: "r"(dst), "l"(src) : "memory")
#define CP_COMMIT() asm volatile("cp.async.commit_group;" ::: "memory")
#define CP_WAIT0()  asm volatile("cp.async.wait_group 0;" ::: "memory")

__device__ __forceinline__ void ldsm4(uint32_t* r, uint32_t a) {
    asm volatile("ldmatrix.sync.aligned.m8n8.x4.shared.b16 {%0,%1,%2,%3}, [%4];"
                 : "=r"(r[0]), "=r"(r[1]), "=r"(r[2]), "=r"(r[3]) : "r"(a));
}
__device__ __forceinline__ void mma_bf16(float* c, const uint32_t* a,
                                         const uint32_t* b) {
    asm volatile(
        "mma.sync.aligned.m16n8k16.row.col.f32.bf16.bf16.f32 "
        "{%0,%1,%2,%3}, {%4,%5,%6,%7}, {%8,%9}, {%0,%1,%2,%3};"
        : "+f"(c[0]), "+f"(c[1]), "+f"(c[2]), "+f"(c[3])
        : "r"(a[0]), "r"(a[1]), "r"(a[2]), "r"(a[3]), "r"(b[0]), "r"(b[1]));
}
__device__ __forceinline__ float gelu_exact(float v) {
    return 0.5f * v * (1.0f + erff(v * 0.7071067811865476f));
}
__device__ __forceinline__ uint32_t pack_hi(float x, float y) {
    __nv_bfloat16 h0 = __float2bfloat16(x), h1 = __float2bfloat16(y);
    return ((uint32_t)__bfloat16_as_ushort(h1) << 16) | __bfloat16_as_ushort(h0);
}
__device__ __forceinline__ uint32_t pack_lo(float x, float y) {
    __nv_bfloat16 h0 = __float2bfloat16(x), h1 = __float2bfloat16(y);
    __nv_bfloat16 l0 = __float2bfloat16(x - __bfloat162float(h0));
    __nv_bfloat16 l1 = __float2bfloat16(y - __bfloat162float(h1));
    return ((uint32_t)__bfloat16_as_ushort(l1) << 16) | __bfloat16_as_ushort(l0);
}
// split a float4 (cols k4..k4+3 of row r) to bf16 hi/lo planes (swizzled)
__device__ __forceinline__ void store_A4(char* aHi, char* aLo, int r, int k4,
                                         float4 v) {
    int off = SWZ(r * 128 + k4 * 2);
    uint2 ph, pl;
    ph.x = pack_hi(v.x, v.y); ph.y = pack_hi(v.z, v.w);
    pl.x = pack_lo(v.x, v.y); pl.y = pack_lo(v.z, v.w);
    *reinterpret_cast<uint2*>(aHi + off) = ph;
    *reinterpret_cast<uint2*>(aLo + off) = pl;
}

// cp.async stage of 256 weight rows x 64 K (hi+lo planes; BLO = BHI+32768)
__device__ __forceinline__ void cp_stage_B(uint32_t smB,
                                           const __nv_bfloat16* __restrict__ h,
                                           const __nv_bfloat16* __restrict__ l,
                                           int nbase, int stride, int k0, int t) {
#pragma unroll
    for (int i = 0; i < 8; ++i) {
        int e = i * NT + t;
        int n = e >> 3, c = e & 7;
        size_t src = (size_t)(nbase + n) * stride + k0 + c * 8;
        uint32_t dst = smB + SWZ(n * 128 + c * 16);
        CP_ASYNC16(dst, h + src);
        CP_ASYNC16(dst + 32768, l + src);
    }
}

// warp MMA tile: 32 rows x (NF2*16) cols over one 64-K chunk, 3-term split.
// ILP ordering: B fragments for 2 nf2 tiles loaded together; MMAs issued
// term-major so same-accumulator reuse distance is 8 instructions.
template <int NF2>
__device__ __forceinline__ void mma_tile(float (*acc)[4], uint32_t aHi,
                                         uint32_t aLo, uint32_t bHi, uint32_t bLo,
                                         int mrow0, int n0, int lane) {
    const int aR = (lane & 7) + ((lane >> 3) & 1) * 8;
    const int aK = ((lane >> 4) & 1) * 16;
    const int bR = (lane & 7) + ((lane >> 4) & 1) * 8;
    const int bK = ((lane >> 3) & 1) * 16;
#pragma unroll
    for (int ks = 0; ks < 4; ++ks) {
        uint32_t ah[2][4], al[2][4];
#pragma unroll
        for (int mf = 0; mf < 2; ++mf) {
            int rel = SWZ((mrow0 + mf * 16 + aR) * 128 + ks * 32 + aK);
            ldsm4(ah[mf], aHi + rel);
            ldsm4(al[mf], aLo + rel);
        }
#pragma unroll
        for (int g = 0; g < NF2 / 2; ++g) {
            uint32_t bh[2][4], bl[2][4];
#pragma unroll
            for (int u = 0; u < 2; ++u) {
                int rel = SWZ((n0 + (g * 2 + u) * 16 + bR) * 128 + ks * 32 + bK);
                ldsm4(bh[u], bHi + rel);
                ldsm4(bl[u], bLo + rel);
            }
            // term 1: hi * hi   (8 distinct accumulators)
#pragma unroll
            for (int u = 0; u < 2; ++u)
#pragma unroll
                for (int mf = 0; mf < 2; ++mf)
#pragma unroll
                    for (int nb = 0; nb < 2; ++nb)
                        mma_bf16(acc[(mf * NF2 + g * 2 + u) * 2 + nb],
                                 ah[mf], bh[u] + nb * 2);
            // term 2: hi * lo
#pragma unroll
            for (int u = 0; u < 2; ++u)
#pragma unroll
                for (int mf = 0; mf < 2; ++mf)
#pragma unroll
                    for (int nb = 0; nb < 2; ++nb)
                        mma_bf16(acc[(mf * NF2 + g * 2 + u) * 2 + nb],
                                 ah[mf], bl[u] + nb * 2);
            // term 3: lo * hi
#pragma unroll
            for (int u = 0; u < 2; ++u)
#pragma unroll
                for (int mf = 0; mf < 2; ++mf)
#pragma unroll
                    for (int nb = 0; nb < 2; ++nb)
                        mma_bf16(acc[(mf * NF2 + g * 2 + u) * 2 + nb],
                                 al[mf], bh[u] + nb * 2);
        }
    }
}

// ---------------- prep: transpose + bf16-split weights ----------------
__global__ void prep_split(const float* __restrict__ w1s, const float* __restrict__ w2s,
                           const float* __restrict__ w1m, const float* __restrict__ w2m) {
    int idx = blockIdx.x * blockDim.x + threadIdx.x;
    if (idx >= HH * DD) return;
    {
        int n = idx / DD, k = idx % DD;
        float v = w1s[(size_t)k * HH + n];
        __nv_bfloat16 h = __float2bfloat16(v);
        g_w1t_hi[0][idx] = h;
        g_w1t_lo[0][idx] = __float2bfloat16(v - __bfloat162float(h));
        v = w1m[(size_t)k * HH + n];
        h = __float2bfloat16(v);
        g_w1t_hi[1][idx] = h;
        g_w1t_lo[1][idx] = __float2bfloat16(v - __bfloat162float(h));
    }
    {
        int n = idx / HH, k = idx % HH;
        float v = w2s[(size_t)k * DD + n];
        __nv_bfloat16 h = __float2bfloat16(v);
        g_w2t_hi[0][idx] = h;
        g_w2t_lo[0][idx] = __float2bfloat16(v - __bfloat162float(h));
        v = w2m[(size_t)k * DD + n];
        h = __float2bfloat16(v);
        g_w2t_hi[1][idx] = h;
        g_w2t_lo[1][idx] = __float2bfloat16(v - __bfloat162float(h));
    }
}

// ---------------- Kernel 1: 32 batch rows/CTA, 4 pools fused as M=128 -------
__global__ void __launch_bounds__(NT, 1)
hdtf_k1(const float* __restrict__ medium, const float* __restrict__ small,
        const float* __restrict__ b1, const float* __restrict__ gam,
        const float* __restrict__ bet, const float* __restrict__ b2) {
    extern __shared__ char sm[];
    uint32_t smb = smem_u32(sm);
    const int t = threadIdx.x, w = t >> 5, lane = t & 31;
    const int wm = w & 3, wn = w >> 2;
    const int row0 = blockIdx.x * 32;
    float* GS = reinterpret_cast<float*>(sm + K1_GS);
    float* RS = reinterpret_cast<float*>(sm + K1_RED);
    float* RQ = RS + 256;

    const int A0[4] = {0, 1, 3, 4}, A1[4] = {1, 2, 4, 5},
              A2[4] = {3, 4, 6, 7}, A3[4] = {4, 5, 7, 8};

    // zero GS (pool-mean accumulator)
    for (int i = t; i < 32 * 256; i += NT) GS[i] = 0.f;

    // A producer: pool 4 smalls per pool block, split, store into buf
    auto produceA = [&](int kc, int buf) {
        char* aHi = sm + K1_A(buf);
        char* aLo = aHi + 16384;
#pragma unroll
        for (int p = 0; p < 4; ++p) {
            const float* s0 = small + (size_t)A0[p] * BN * DD;
            const float* s1 = small + (size_t)A1[p] * BN * DD;
            const float* s2 = small + (size_t)A2[p] * BN * DD;
            const float* s3 = small + (size_t)A3[p] * BN * DD;
#pragma unroll
            for (int i = 0; i < 2; ++i) {
                int e = i * NT + t;
                int br = e >> 4, k4 = (e & 15) << 2;
                size_t off = (size_t)(row0 + br) * DD + kc * 64 + k4;
                float4 a = *reinterpret_cast<const float4*>(s0 + off);
                float4 b = *reinterpret_cast<const float4*>(s1 + off);
                float4 c = *reinterpret_cast<const float4*>(s2 + off);
                float4 d = *reinterpret_cast<const float4*>(s3 + off);
                float4 v;
                v.x = 0.25f * (a.x + b.x + c.x + d.x);
                v.y = 0.25f * (a.y + b.y + c.y + d.y);
                v.z = 0.25f * (a.z + b.z + c.z + d.z);
                v.w = 0.25f * (a.w + b.w + c.w + d.w);
                store_A4(aHi, aLo, p * 32 + br, k4, v);
            }
        }
    };

    // ---- GEMM1 pipeline: M=128, N=256, K=768 (12 chunks) ----
    float acc[32][4];
#pragma unroll
    for (int i = 0; i < 32; ++i) { acc[i][0]=acc[i][1]=acc[i][2]=acc[i][3]=0.f; }

    produceA(0, 0);
    cp_stage_B(smb + K1_B(0), g_w1t_hi[0], g_w1t_lo[0], 0, DD, 0, t);
    CP_COMMIT();

    for (int kc = 0; kc < 12; ++kc) {
        int cur = kc & 1, nxt = cur ^ 1;
        CP_WAIT0();
        __syncthreads();
        if (kc < 11) {
            cp_stage_B(smb + K1_B(nxt), g_w1t_hi[0], g_w1t_lo[0], 0, DD,
                       (kc + 1) * 64, t);
            CP_COMMIT();
        }
        mma_tile<8>(acc, smb + K1_A(cur), smb + K1_A(cur) + 16384,
                    smb + K1_B(cur), smb + K1_B(cur) + 32768,
                    wm * 32, wn * 128, lane);
        if (kc < 11) produceA(kc + 1, nxt);
    }

    // ---- epilogue: bias + LN(128 rows) + GELU + pool-mean (atomic) ----
    {
        float s[4] = {0, 0, 0, 0}, q[4] = {0, 0, 0, 0};
#pragma unroll
        for (int mf = 0; mf < 2; ++mf)
#pragma unroll
            for (int nf = 0; nf < 16; ++nf) {
                int c = wn * 128 + nf * 8 + 2 * (lane & 3);
                float2 bb = *reinterpret_cast<const float2*>(b1 + c);
                float* a = acc[mf * 16 + nf];
                a[0] += bb.x; a[1] += bb.y; a[2] += bb.x; a[3] += bb.y;
                s[mf * 2]     += a[0] + a[1];
                q[mf * 2]     += a[0] * a[0] + a[1] * a[1];
                s[mf * 2 + 1] += a[2] + a[3];
                q[mf * 2 + 1] += a[2] * a[2] + a[3] * a[3];
            }
#pragma unroll
        for (int h = 0; h < 4; ++h) {
            s[h] += __shfl_xor_sync(0xffffffffu, s[h], 1);
            s[h] += __shfl_xor_sync(0xffffffffu, s[h], 2);
            q[h] += __shfl_xor_sync(0xffffffffu, q[h], 1);
            q[h] += __shfl_xor_sync(0xffffffffu, q[h], 2);
        }
        if ((lane & 3) == 0) {
#pragma unroll
            for (int h = 0; h < 4; ++h) {
                int r = wm * 32 + (lane >> 2) + (h & 1) * 8 + (h >> 1) * 16;
                RS[r * 2 + wn] = s[h];
                RQ[r * 2 + wn] = q[h];
            }
        }
        __syncthreads();
        float mu[4], ri[4];
#pragma unroll
        for (int h = 0; h < 4; ++h) {
            int r = wm * 32 + (lane >> 2) + (h & 1) * 8 + (h >> 1) * 16;
            float ss = RS[r * 2] + RS[r * 2 + 1];
            float qq = RQ[r * 2] + RQ[r * 2 + 1];
            mu[h] = ss * (1.0f / HH);
            ri[h] = rsqrtf(qq * (1.0f / HH) - mu[h] * mu[h] + LN_EPS);
        }
#pragma unroll
        for (int mf = 0; mf < 2; ++mf)
#pragma unroll
            for (int nf = 0; nf < 16; ++nf) {
                int c = wn * 128 + nf * 8 + 2 * (lane & 3);
                float2 gg = *reinterpret_cast<const float2*>(gam + c);
                float2 ee = *reinterpret_cast<const float2*>(bet + c);
                float* a = acc[mf * 16 + nf];
#pragma unroll
                for (int hh = 0; hh < 2; ++hh) {
                    int h = mf * 2 + hh;
                    int rl = (lane >> 2) + mf * 16 + hh * 8;   // 0..31 in pool wm
                    float v0 = (a[hh * 2]     - mu[h]) * ri[h] * gg.x + ee.x;
                    float v1 = (a[hh * 2 + 1] - mu[h]) * ri[h] * gg.y + ee.y;
                    atomicAdd(&GS[rl * 256 + c],     0.25f * gelu_exact(v0));
                    atomicAdd(&GS[rl * 256 + c + 1], 0.25f * gelu_exact(v1));
                }
            }
    }
    __syncthreads();

    // ---- GEMM2 pipeline: GS[32x256] @ W2 (N=768), 12 chunks flattened ----
    auto produceA2 = [&](int cc, int buf) {
        char* aHi = sm + K1_A(buf);
        char* aLo = aHi + 16384;
        int kc = cc & 3;
#pragma unroll
        for (int i = 0; i < 2; ++i) {
            int e = i * NT + t;
            int r = e >> 4, k4 = (e & 15) << 2;
            float4 v = *reinterpret_cast<float4*>(&GS[r * 256 + kc * 64 + k4]);
            store_A4(aHi, aLo, r, k4, v);
        }
    };

    float a2[8][4];
#pragma unroll
    for (int i = 0; i < 8; ++i) { a2[i][0]=a2[i][1]=a2[i][2]=a2[i][3]=0.f; }

    produceA2(0, 0);
    cp_stage_B(smb + K1_B(0), g_w2t_hi[0], g_w2t_lo[0], 0, HH, 0, t);
    CP_COMMIT();

    for (int cc = 0; cc < 12; ++cc) {
        int cur = cc & 1, nxt = cur ^ 1;
        CP_WAIT0();
        __syncthreads();
        if (cc < 11) {
            int c2 = cc + 1;
            cp_stage_B(smb + K1_B(nxt), g_w2t_hi[0], g_w2t_lo[0],
                       (c2 >> 2) * 256, HH, (c2 & 3) * 64, t);
            CP_COMMIT();
        }
        mma_tile<2>(a2, smb + K1_A(cur), smb + K1_A(cur) + 16384,
                    smb + K1_B(cur), smb + K1_B(cur) + 32768,
                    0, w * 32, lane);
        if (cc < 11) produceA2(cc + 1, nxt);

        if ((cc & 3) == 3) {
            int nt = cc >> 2;
#pragma unroll
            for (int mf = 0; mf < 2; ++mf)
#pragma unroll
                for (int nf = 0; nf < 4; ++nf) {
                    int c = nt * 256 + w * 32 + nf * 8 + 2 * (lane & 3);
                    float2 bb = *reinterpret_cast<const float2*>(b2 + c);
                    float* a = a2[mf * 4 + nf];
#pragma unroll
                    for (int hh = 0; hh < 2; ++hh) {
                        int r = (lane >> 2) + mf * 16 + hh * 8;
                        int grow = row0 + r;
                        float2 m0 = *reinterpret_cast<const float2*>(medium + ((size_t)0 * BN + grow) * DD + c);
                        float2 m1 = *reinterpret_cast<const float2*>(medium + ((size_t)1 * BN + grow) * DD + c);
                        float2 m2 = *reinterpret_cast<const float2*>(medium + ((size_t)2 * BN + grow) * DD + c);
                        float2 m3 = *reinterpret_cast<const float2*>(medium + ((size_t)3 * BN + grow) * DD + c);
                        float ox = a[hh * 2]     + bb.x + 0.25f * (m0.x + m1.x + m2.x + m3.x);
                        float oy = a[hh * 2 + 1] + bb.y + 0.25f * (m0.y + m1.y + m2.y + m3.y);
                        size_t gi = ((size_t)grow * DD + c) >> 1;
                        reinterpret_cast<uint32_t*>(g_mp_hi)[gi] = pack_hi(ox, oy);
                        reinterpret_cast<uint32_t*>(g_mp_lo)[gi] = pack_lo(ox, oy);
                    }
                }
#pragma unroll
            for (int i = 0; i < 8; ++i) { a2[i][0]=a2[i][1]=a2[i][2]=a2[i][3]=0.f; }
        }
    }
}

// ---------------- Kernel 2: 64 batch rows/CTA, MLP2 + global add ------------
__global__ void __launch_bounds__(NT, 1)
hdtf_k2(const float* __restrict__ gfeat,
        const float* __restrict__ b1, const float* __restrict__ gam,
        const float* __restrict__ bet, const float* __restrict__ b2,
        float* __restrict__ out) {
    extern __shared__ char sm[];
    uint32_t smb = smem_u32(sm);
    const int t = threadIdx.x, w = t >> 5, lane = t & 31;
    const int wm = w & 1, wn = w >> 1;       // 2 x 4 warp grid (32 x 64 tiles)
    const int row0 = blockIdx.x * 64;
    float* RS = reinterpret_cast<float*>(sm + K2_RED);
    float* RQ = RS + 256;

    // A stage: cp.async g_mp hi/lo planes (64 rows x 64 K)
    auto cpA = [&](int kc, int buf) {
        uint32_t aHi = smb + K2_A(buf);
#pragma unroll
        for (int i = 0; i < 2; ++i) {
            int e = i * NT + t;
            int r = e >> 3, c = e & 7;
            size_t src = (size_t)(row0 + r) * DD + kc * 64 + c * 8;
            uint32_t dst = aHi + SWZ(r * 128 + c * 16);
            CP_ASYNC16(dst, g_mp_hi + src);
            CP_ASYNC16(dst + 8192, g_mp_lo + src);
        }
    };

    // ---- GEMM1 pipeline: M=64, N=256, K=768 ----
    float acc[16][4];
#pragma unroll
    for (int i = 0; i < 16; ++i) { acc[i][0]=acc[i][1]=acc[i][2]=acc[i][3]=0.f; }

    cpA(0, 0);
    cp_stage_B(smb + K2_B(0), g_w1t_hi[1], g_w1t_lo[1], 0, DD, 0, t);
    CP_COMMIT();

    for (int kc = 0; kc < 12; ++kc) {
        int cur = kc & 1, nxt = cur ^ 1;
        CP_WAIT0();
        __syncthreads();
        if (kc < 11) {
            cpA(kc + 1, nxt);
            cp_stage_B(smb + K2_B(nxt), g_w1t_hi[1], g_w1t_lo[1], 0, DD,
                       (kc + 1) * 64, t);
            CP_COMMIT();
        }
        mma_tile<4>(acc, smb + K2_A(cur), smb + K2_A(cur) + 8192,
                    smb + K2_B(cur), smb + K2_B(cur) + 32768,
                    wm * 32, wn * 64, lane);
    }

    // ---- epilogue: bias + LN(64 rows) + GELU -> GS split/swizzled ----
    {
        float s[4] = {0, 0, 0, 0}, q[4] = {0, 0, 0, 0};
#pragma unroll
        for (int mf = 0; mf < 2; ++mf)
#pragma unroll
            for (int nf = 0; nf < 8; ++nf) {
                int c = wn * 64 + nf * 8 + 2 * (lane & 3);
                float2 bb = *reinterpret_cast<const float2*>(b1 + c);
                float* a = acc[mf * 8 + nf];
                a[0] += bb.x; a[1] += bb.y; a[2] += bb.x; a[3] += bb.y;
                s[mf * 2]     += a[0] + a[1];
                q[mf * 2]     += a[0] * a[0] + a[1] * a[1];
                s[mf * 2 + 1] += a[2] + a[3];
                q[mf * 2 + 1] += a[2] * a[2] + a[3] * a[3];
            }
#pragma unroll
        for (int h = 0; h < 4; ++h) {
            s[h] += __shfl_xor_sync(0xffffffffu, s[h], 1);
            s[h] += __shfl_xor_sync(0xffffffffu, s[h], 2);
            q[h] += __shfl_xor_sync(0xffffffffu, q[h], 1);
            q[h] += __shfl_xor_sync(0xffffffffu, q[h], 2);
        }
        if ((lane & 3) == 0) {
#pragma unroll
            for (int h = 0; h < 4; ++h) {
                int r = wm * 32 + (lane >> 2) + (h & 1) * 8 + (h >> 1) * 16;
                RS[r * 4 + wn] = s[h];
                RQ[r * 4 + wn] = q[h];
            }
        }
        __syncthreads();
        float mu[4], ri[4];
#pragma unroll
        for (int h = 0; h < 4; ++h) {
            int r = wm * 32 + (lane >> 2) + (h & 1) * 8 + (h >> 1) * 16;
            float ss = RS[r * 4] + RS[r * 4 + 1] + RS[r * 4 + 2] + RS[r * 4 + 3];
            float qq = RQ[r * 4] + RQ[r * 4 + 1] + RQ[r * 4 + 2] + RQ[r * 4 + 3];
            mu[h] = ss * (1.0f / HH);
            ri[h] = rsqrtf(qq * (1.0f / HH) - mu[h] * mu[h] + LN_EPS);
        }
#pragma unroll
        for (int mf = 0; mf < 2; ++mf)
#pragma unroll
            for (int nf = 0; nf < 8; ++nf) {
                int c = wn * 64 + nf * 8 + 2 * (lane & 3);
                float2 gg = *reinterpret_cast<const float2*>(gam + c);
                float2 ee = *reinterpret_cast<const float2*>(bet + c);
                float* a = acc[mf * 8 + nf];
#pragma unroll
                for (int hh = 0; hh < 2; ++hh) {
                    int h = mf * 2 + hh;
                    int r = wm * 32 + (lane >> 2) + mf * 16 + hh * 8;
                    float v0 = gelu_exact((a[hh * 2]     - mu[h]) * ri[h] * gg.x + ee.x);
                    float v1 = gelu_exact((a[hh * 2 + 1] - mu[h]) * ri[h] * gg.y + ee.y);
                    int chunk = c >> 6;
                    int off = chunk * 8192 + SWZ(r * 128 + (c & 63) * 2);
                    *reinterpret_cast<uint32_t*>(sm + K2_GSH + off) = pack_hi(v0, v1);
                    *reinterpret_cast<uint32_t*>(sm + K2_GSL + off) = pack_lo(v0, v1);
                }
            }
    }
    __syncthreads();

    // ---- GEMM2 pipeline: GS[64x256] @ W2 (N=768); A read in-place from GS ---
#pragma unroll
    for (int i = 0; i < 16; ++i) { acc[i][0]=acc[i][1]=acc[i][2]=acc[i][3]=0.f; }

    cp_stage_B(smb + K2_B(0), g_w2t_hi[1], g_w2t_lo[1], 0, HH, 0, t);
    CP_COMMIT();

    for (int cc = 0; cc < 12; ++cc) {
        int cur = cc & 1, nxt = cur ^ 1;
        CP_WAIT0();
        __syncthreads();
        if (cc < 11) {
            int c2 = cc + 1;
            cp_stage_B(smb + K2_B(nxt), g_w2t_hi[1], g_w2t_lo[1],
                       (c2 >> 2) * 256, HH, (c2 & 3) * 64, t);
            CP_COMMIT();
        }
        int kc = cc & 3;
        mma_tile<4>(acc, smb + K2_GSH + kc * 8192, smb + K2_GSL + kc * 8192,
                    smb + K2_B(cur), smb + K2_B(cur) + 32768,
                    wm * 32, wn * 64, lane);

        if ((cc & 3) == 3) {
            int nt = cc >> 2;
#pragma unroll
            for (int mf = 0; mf < 2; ++mf)
#pragma unroll
                for (int nf = 0; nf < 8; ++nf) {
                    int c = nt * 256 + wn * 64 + nf * 8 + 2 * (lane & 3);
                    float2 bb = *reinterpret_cast<const float2*>(b2 + c);
                    float* a = acc[mf * 8 + nf];
#pragma unroll
                    for (int hh = 0; hh < 2; ++hh) {
                        int r = wm * 32 + (lane >> 2) + mf * 16 + hh * 8;
                        int grow = row0 + r;
                        float2 gv = *reinterpret_cast<const float2*>(
                            gfeat + (size_t)grow * DD + c);
                        float2 o;
                        o.x = a[hh * 2]     + bb.x + gv.x;
                        o.y = a[hh * 2 + 1] + bb.y + gv.y;
                        *reinterpret_cast<float2*>(&out[(size_t)grow * DD + c]) = o;
                    }
                }
#pragma unroll
            for (int i = 0; i < 16; ++i) { acc[i][0]=acc[i][1]=acc[i][2]=acc[i][3]=0.f; }
        }
    }
}

// ---------------- launch ----------------
extern "C" void kernel_launch(void* const* d_in, const int* in_sizes, int n_in,
                              void* d_out, int out_size) {
    const float* global_feat = (const float*)d_in[0];
    const float* medium      = (const float*)d_in[1];
    const float* small       = (const float*)d_in[2];
    const float* sm_w1 = (const float*)d_in[3];
    const float* sm_b1 = (const float*)d_in[4];
    const float* sm_g  = (const float*)d_in[5];
    const float* sm_be = (const float*)d_in[6];
    const float* sm_w2 = (const float*)d_in[7];
    const float* sm_b2 = (const float*)d_in[8];
    const float* mg_w1 = (const float*)d_in[9];
    const float* mg_b1 = (const float*)d_in[10];
    const float* mg_g  = (const float*)d_in[11];
    const float* mg_be = (const float*)d_in[12];
    const float* mg_w2 = (const float*)d_in[13];
    const float* mg_b2 = (const float*)d_in[14];
    float* out = (float*)d_out;

    cudaFuncSetAttribute(hdtf_k1, cudaFuncAttributeMaxDynamicSharedMemorySize, K1_SMEM);
    cudaFuncSetAttribute(hdtf_k2, cudaFuncAttributeMaxDynamicSharedMemorySize, K2_SMEM);

    prep_split<<<(HH * DD + 255) / 256, 256>>>(sm_w1, sm_w2, mg_w1, mg_w2);
    hdtf_k1<<<BN / 32, NT, K1_SMEM>>>(medium, small, sm_b1, sm_g, sm_be, sm_b2);
    hdtf_k2<<<BN / 64, NT, K2_SMEM>>>(global_feat, mg_b1, mg_g, mg_be, mg_b2, out);
}